// round 1
// baseline (speedup 1.0000x reference)
#include <cuda_runtime.h>

// Shapes: B=8, C=256, N=1024, V=12, H=4, D=64. NV = N*V = 12288.
// Key identity: attention output == v (softmax over j sums to 1; j only indexes attn).
// Pipeline: 4 masked-BN 1x1 convs (GEMMs) + residuals.

#define NVC 12288
#define NB 8
#define CNT_INV (1.0f/98304.0f)
#define EPS 1e-5f

// Scratch (device globals: allocation-free rule)
__device__ float g_emb[NB * 64 * NVC];     // 25.2 MB
__device__ float g_bufa[NB * 256 * NVC];   // 100.7 MB
__device__ float g_bufb[NB * 256 * NVC];   // 100.7 MB
__device__ float g_stats[2048];            // per-layer channel sums / sumsqs

__global__ void zero_stats() {
    int i = blockIdx.x * blockDim.x + threadIdx.x;
    if (i < 2048) g_stats[i] = 0.0f;
}

// Y[b, m, col] = sum_k W[m,k] * X[b,k,col] + bias[m], then *mask, write Y,
// and atomically accumulate per-channel sum/sumsq for batch-stat BN.
// BN(cols)=128 tile, BK=16, TN=8. THREADS must be 256.
template<int M, int K, int BM, int TM>
__global__ void __launch_bounds__(256)
gemm_stats(const float* __restrict__ X, const float* __restrict__ W,
           const float* __restrict__ bias, const float* __restrict__ mask,
           float* __restrict__ Y, float* __restrict__ ssum, float* __restrict__ ssq)
{
    constexpr int BN = 128, BK = 16, TN = 8;
    constexpr int THREADS = (BM / TM) * (BN / TN);
    static_assert(THREADS == 256, "bad tile config");

    __shared__ float Ws[BK][BM + 4];
    __shared__ float Xs[BK][BN];
    __shared__ float rs[BM];
    __shared__ float rq[BM];

    const int b    = blockIdx.z;
    const int row0 = blockIdx.y * BM;
    const int col0 = blockIdx.x * BN;
    const float* Xb = X + (size_t)b * K * NVC;
    float*       Yb = Y + (size_t)b * M * NVC;

    const int tid   = threadIdx.x;
    const int tx    = tid & 15;        // BN/TN = 16
    const int ty    = tid >> 4;        // BM/TM = 16
    const int rbase = ty * TM;
    const int cbase = tx * TN;

    float acc[TM][TN];
#pragma unroll
    for (int i = 0; i < TM; i++)
#pragma unroll
        for (int j = 0; j < TN; j++) acc[i][j] = 0.0f;

#pragma unroll 1
    for (int k0 = 0; k0 < K; k0 += BK) {
        // W tile [BM x BK] -> Ws[k][m]
#pragma unroll
        for (int l = tid; l < BM * BK; l += THREADS) {
            int m = l >> 4, kk = l & 15;
            Ws[kk][m] = W[(size_t)(row0 + m) * K + k0 + kk];
        }
        // X tile [BK x BN], vectorized
#pragma unroll
        for (int l = tid; l < BK * (BN / 4); l += THREADS) {
            int kk = l >> 5, c4 = l & 31;   // BN/4 = 32
            *reinterpret_cast<float4*>(&Xs[kk][c4 * 4]) =
                *reinterpret_cast<const float4*>(Xb + (size_t)(k0 + kk) * NVC + col0 + c4 * 4);
        }
        __syncthreads();

#pragma unroll
        for (int kk = 0; kk < BK; kk++) {
            alignas(16) float wr[TM];
            alignas(16) float xr[TN];
#pragma unroll
            for (int i = 0; i < TM; i += 4)
                *reinterpret_cast<float4*>(wr + i) =
                    *reinterpret_cast<const float4*>(&Ws[kk][rbase + i]);
#pragma unroll
            for (int j = 0; j < TN; j += 4)
                *reinterpret_cast<float4*>(xr + j) =
                    *reinterpret_cast<const float4*>(&Xs[kk][cbase + j]);
#pragma unroll
            for (int i = 0; i < TM; i++)
#pragma unroll
                for (int j = 0; j < TN; j++)
                    acc[i][j] = fmaf(wr[i], xr[j], acc[i][j]);
        }
        __syncthreads();
    }

    // Epilogue: bias, mask, store, per-channel stats
    for (int l = tid; l < BM; l += THREADS) { rs[l] = 0.0f; rq[l] = 0.0f; }
    __syncthreads();

    alignas(16) float mv[TN];
#pragma unroll
    for (int j = 0; j < TN; j += 4)
        *reinterpret_cast<float4*>(mv + j) =
            *reinterpret_cast<const float4*>(mask + (size_t)b * NVC + col0 + cbase + j);

#pragma unroll
    for (int i = 0; i < TM; i++) {
        const int m = rbase + i;
        const float bv = bias[row0 + m];
        float s = 0.0f, q = 0.0f;
        alignas(16) float yv[TN];
#pragma unroll
        for (int j = 0; j < TN; j++) {
            float y = (acc[i][j] + bv) * mv[j];
            yv[j] = y;
            s += y;
            q += y * y;
        }
#pragma unroll
        for (int j = 0; j < TN; j += 4)
            *reinterpret_cast<float4*>(Yb + (size_t)(row0 + m) * NVC + col0 + cbase + j) =
                *reinterpret_cast<const float4*>(yv + j);
        atomicAdd(&rs[m], s);
        atomicAdd(&rq[m], q);
    }
    __syncthreads();
    for (int l = tid; l < BM; l += THREADS) {
        atomicAdd(&ssum[row0 + l], rs[l]);
        atomicAdd(&ssq[row0 + l], rq[l]);
    }
}

// out = [mask>0 ? relu((y-mu)*rstd*g + bt) : 0] (+ res if RES)
template<int M, bool RES>
__global__ void __launch_bounds__(256)
bn_relu(const float* __restrict__ Yin, const float* __restrict__ mask,
        const float* __restrict__ ssum, const float* __restrict__ ssq,
        const float* __restrict__ gam, const float* __restrict__ bet,
        const float* __restrict__ res, float* __restrict__ out)
{
    size_t i = (size_t)blockIdx.x * blockDim.x + threadIdx.x;
    constexpr size_t TOT4 = (size_t)NB * M * NVC / 4;
    if (i >= TOT4) return;
    size_t e = i * 4;
    int col = (int)(e % NVC);
    size_t bm = e / NVC;
    int m = (int)(bm % M);
    int b = (int)(bm / M);

    float mu  = ssum[m] * CNT_INV;
    float var = fmaf(-mu, mu, ssq[m] * CNT_INV);
    float a   = gam[m] * rsqrtf(var + EPS);
    float c   = fmaf(-mu, a, bet[m]);

    float4 y  = *reinterpret_cast<const float4*>(Yin + e);
    float4 mk = *reinterpret_cast<const float4*>(mask + (size_t)b * NVC + col);
    float4 o;
    o.x = mk.x > 0.0f ? fmaxf(fmaf(y.x, a, c), 0.0f) : 0.0f;
    o.y = mk.y > 0.0f ? fmaxf(fmaf(y.y, a, c), 0.0f) : 0.0f;
    o.z = mk.z > 0.0f ? fmaxf(fmaf(y.z, a, c), 0.0f) : 0.0f;
    o.w = mk.w > 0.0f ? fmaxf(fmaf(y.w, a, c), 0.0f) : 0.0f;
    if (RES) {
        float4 r = *reinterpret_cast<const float4*>(res + e);
        o.x += r.x; o.y += r.y; o.z += r.z; o.w += r.w;
    }
    *reinterpret_cast<float4*>(out + e) = o;
}

extern "C" void kernel_launch(void* const* d_in, const int* in_sizes, int n_in,
                              void* d_out, int out_size)
{
    const float* feats = (const float*)d_in[0];
    const float* mask  = (const float*)d_in[1];
    const float* We    = (const float*)d_in[2];
    const float* be    = (const float*)d_in[3];
    const float* ge    = (const float*)d_in[4];
    const float* bne   = (const float*)d_in[5];
    const float* Wa    = (const float*)d_in[6];
    const float* ba    = (const float*)d_in[7];
    const float* ga    = (const float*)d_in[8];
    const float* bna   = (const float*)d_in[9];
    const float* Wo    = (const float*)d_in[10];
    const float* bo    = (const float*)d_in[11];
    const float* go    = (const float*)d_in[12];
    const float* bno   = (const float*)d_in[13];
    const float* Wf    = (const float*)d_in[14];
    const float* bf    = (const float*)d_in[15];
    const float* gf    = (const float*)d_in[16];
    const float* bnf   = (const float*)d_in[17];
    float* out = (float*)d_out;

    float *emb, *bufa, *bufb, *st;
    cudaGetSymbolAddress((void**)&emb,  g_emb);
    cudaGetSymbolAddress((void**)&bufa, g_bufa);
    cudaGetSymbolAddress((void**)&bufb, g_bufb);
    cudaGetSymbolAddress((void**)&st,   g_stats);

    zero_stats<<<8, 256>>>();

    // vconv-e: emb = BNReLU(We @ feats + be)   [64 channels]
    gemm_stats<64, 256, 64, 4><<<dim3(NVC / 128, 1, NB), 256>>>(
        feats, We, be, mask, emb, st + 0, st + 64);
    bn_relu<64, false><<<(NB * 64 * NVC / 4) / 256, 256>>>(
        emb, mask, st + 0, st + 64, ge, bne, nullptr, emb);

    // vconv-a (v-slice only, rows [512:768) of Wa): v = BNReLU(Wa_v @ emb + ba_v)
    // (attention output == v, since softmax over j sums to 1)
    gemm_stats<256, 64, 128, 8><<<dim3(NVC / 128, 2, NB), 256>>>(
        emb, Wa + 512 * 64, ba + 512, mask, bufa, st + 128, st + 384);
    bn_relu<256, false><<<(NB * 256 * NVC / 4) / 256, 256>>>(
        bufa, mask, st + 128, st + 384, ga + 512, bna + 512, nullptr, bufa);

    // vconv-o + residual: x1 = feats + BNReLU(Wo @ v + bo)
    gemm_stats<256, 256, 128, 8><<<dim3(NVC / 128, 2, NB), 256>>>(
        bufa, Wo, bo, mask, bufb, st + 640, st + 896);
    bn_relu<256, true><<<(NB * 256 * NVC / 4) / 256, 256>>>(
        bufb, mask, st + 640, st + 896, go, bno, feats, bufa);

    // vconv-f + residual: out = x1 + BNReLU(Wf @ x1 + bf)
    gemm_stats<256, 256, 128, 8><<<dim3(NVC / 128, 2, NB), 256>>>(
        bufa, Wf, bf, mask, bufb, st + 1152, st + 1408);
    bn_relu<256, true><<<(NB * 256 * NVC / 4) / 256, 256>>>(
        bufb, mask, st + 1152, st + 1408, gf, bnf, bufa, out);
}